// round 2
// baseline (speedup 1.0000x reference)
#include <cuda_runtime.h>

// Closed form (derived R0, verified): theta_i = x[b,i]+w[i], c_i = cos(2*theta_i)
//   out[b] = { c1*c2*c3, c0*c1, c0*c1*c2, c0*c1*c2*c3 }
// R2: __cosf (MUFU.COS) instead of software cosf — kernel was issue-bound
// on the range-reduction instruction stream, not on HBM.

#define V4_PER_THREAD 4

__global__ void __launch_bounds__(256)
hilbert_closed_form(const float4* __restrict__ x4,
                    const float* __restrict__ w,
                    float4* __restrict__ out4,
                    int n)   // n = number of float4 elements
{
    int base = (blockIdx.x * blockDim.x + threadIdx.x) * V4_PER_THREAD;

    float w0 = 2.0f * w[0], w1 = 2.0f * w[1];
    float w2 = 2.0f * w[2], w3 = 2.0f * w[3];

    // Front-batched loads: MLP = V4_PER_THREAD
    float4 xv[V4_PER_THREAD];
#pragma unroll
    for (int k = 0; k < V4_PER_THREAD; k++) {
        int i = base + k;
        if (i < n) xv[k] = x4[i];
    }

#pragma unroll
    for (int k = 0; k < V4_PER_THREAD; k++) {
        int i = base + k;
        if (i >= n) break;

        float c0 = __cosf(fmaf(2.0f, xv[k].x, w0));
        float c1 = __cosf(fmaf(2.0f, xv[k].y, w1));
        float c2 = __cosf(fmaf(2.0f, xv[k].z, w2));
        float c3 = __cosf(fmaf(2.0f, xv[k].w, w3));

        float t01  = c0 * c1;
        float t012 = t01 * c2;

        float4 o;
        o.x = c1 * c2 * c3;
        o.y = t01;
        o.z = t012;
        o.w = t012 * c3;

        out4[i] = o;
    }
}

extern "C" void kernel_launch(void* const* d_in, const int* in_sizes, int n_in,
                              void* d_out, int out_size)
{
    const float* x = (const float*)d_in[0];
    const float* w = (const float*)d_in[1];
    int nx = in_sizes[0];
    if (n_in >= 2 && in_sizes[0] < in_sizes[1]) {
        x = (const float*)d_in[1];
        w = (const float*)d_in[0];
        nx = in_sizes[1];
    }

    int n = nx / 4;  // float4 count (= batch)
    int threads = 256;
    int per_block = threads * V4_PER_THREAD;
    int blocks = (n + per_block - 1) / per_block;

    hilbert_closed_form<<<blocks, threads>>>(
        (const float4*)x, w, (float4*)d_out, n);
}

// round 3
// speedup vs baseline: 1.5073x; 1.5073x over previous
#include <cuda_runtime.h>

// Closed form (derived R0): theta_i = x[b,i]+w[i], c_i = cos(2*theta_i)
//   out[b] = { c1*c2*c3, c0*c1, c0*c1*c2, c0*c1*c2*c3 }
//
// R3: latency-bound fix — exact single wave (1024 CTAs x 256 thr, 8 float4s
// per thread, strided/coalesced) + 2-stage software pipeline so batch B's
// loads are in flight while batch A computes/stores.

#define NTHREADS 256
#define NBLOCKS  1024                       // T = 262144 threads
#define TSTRIDE  (NTHREADS * NBLOCKS)       // elements between a thread's items

__device__ __forceinline__ void compute_store(float4 xv, float w0, float w1,
                                              float w2, float w3,
                                              float4* __restrict__ dst)
{
    float c0 = __cosf(fmaf(2.0f, xv.x, w0));
    float c1 = __cosf(fmaf(2.0f, xv.y, w1));
    float c2 = __cosf(fmaf(2.0f, xv.z, w2));
    float c3 = __cosf(fmaf(2.0f, xv.w, w3));
    float t01  = c0 * c1;
    float t012 = t01 * c2;
    float4 o;
    o.x = c1 * c2 * c3;
    o.y = t01;
    o.z = t012;
    o.w = t012 * c3;
    *dst = o;
}

// Fast path: n == 8 * TSTRIDE exactly (BATCH = 2^21).
__global__ void __launch_bounds__(NTHREADS, 7)
hilbert_fast(const float4* __restrict__ x4,
             const float* __restrict__ w,
             float4* __restrict__ out4)
{
    int tid = blockIdx.x * NTHREADS + threadIdx.x;

    float w0 = 2.0f * w[0], w1 = 2.0f * w[1];
    float w2 = 2.0f * w[2], w3 = 2.0f * w[3];

    // ---- stage A: load 4 (MLP=4) ----
    float4 a0 = x4[tid + 0 * TSTRIDE];
    float4 a1 = x4[tid + 1 * TSTRIDE];
    float4 a2 = x4[tid + 2 * TSTRIDE];
    float4 a3 = x4[tid + 3 * TSTRIDE];

    // consume A into cos values (frees a0..a3's registers)
    float ca[16];
    {
        float4 av[4] = {a0, a1, a2, a3};
#pragma unroll
        for (int k = 0; k < 4; k++) {
            ca[4*k+0] = __cosf(fmaf(2.0f, av[k].x, w0));
            ca[4*k+1] = __cosf(fmaf(2.0f, av[k].y, w1));
            ca[4*k+2] = __cosf(fmaf(2.0f, av[k].z, w2));
            ca[4*k+3] = __cosf(fmaf(2.0f, av[k].w, w3));
        }
    }

    // ---- stage B loads in flight while A finishes ----
    float4 b0 = x4[tid + 4 * TSTRIDE];
    float4 b1 = x4[tid + 5 * TSTRIDE];
    float4 b2 = x4[tid + 6 * TSTRIDE];
    float4 b3 = x4[tid + 7 * TSTRIDE];

    // ---- store A results ----
#pragma unroll
    for (int k = 0; k < 4; k++) {
        float c0 = ca[4*k+0], c1 = ca[4*k+1], c2 = ca[4*k+2], c3 = ca[4*k+3];
        float t01  = c0 * c1;
        float t012 = t01 * c2;
        float4 o;
        o.x = c1 * c2 * c3;
        o.y = t01;
        o.z = t012;
        o.w = t012 * c3;
        out4[tid + k * TSTRIDE] = o;
    }

    // ---- compute + store B ----
    compute_store(b0, w0, w1, w2, w3, &out4[tid + 4 * TSTRIDE]);
    compute_store(b1, w0, w1, w2, w3, &out4[tid + 5 * TSTRIDE]);
    compute_store(b2, w0, w1, w2, w3, &out4[tid + 6 * TSTRIDE]);
    compute_store(b3, w0, w1, w2, w3, &out4[tid + 7 * TSTRIDE]);
}

// Generic fallback (any n of float4s).
__global__ void __launch_bounds__(256)
hilbert_generic(const float4* __restrict__ x4,
                const float* __restrict__ w,
                float4* __restrict__ out4, int n)
{
    int i = blockIdx.x * blockDim.x + threadIdx.x;
    if (i >= n) return;
    float w0 = 2.0f * w[0], w1 = 2.0f * w[1];
    float w2 = 2.0f * w[2], w3 = 2.0f * w[3];
    compute_store(x4[i], w0, w1, w2, w3, &out4[i]);
}

extern "C" void kernel_launch(void* const* d_in, const int* in_sizes, int n_in,
                              void* d_out, int out_size)
{
    const float* x = (const float*)d_in[0];
    const float* w = (const float*)d_in[1];
    int nx = in_sizes[0];
    if (n_in >= 2 && in_sizes[0] < in_sizes[1]) {
        x = (const float*)d_in[1];
        w = (const float*)d_in[0];
        nx = in_sizes[1];
    }

    int n = nx / 4;  // float4 count (= batch)

    if (n == 8 * TSTRIDE) {
        hilbert_fast<<<NBLOCKS, NTHREADS>>>(
            (const float4*)x, w, (float4*)d_out);
    } else {
        int threads = 256;
        int blocks = (n + threads - 1) / threads;
        hilbert_generic<<<blocks, threads>>>(
            (const float4*)x, w, (float4*)d_out, n);
    }
}

// round 4
// speedup vs baseline: 1.5433x; 1.0239x over previous
#include <cuda_runtime.h>

// Closed form (derived R0): theta_i = x[b,i]+w[i], c_i = cos(2*theta_i)
//   out[b] = { c1*c2*c3, c0*c1, c0*c1*c2, c0*c1*c2*c3 }
//
// R4: finer balance (128-thr CTAs, 2048 blocks, single fully-resident wave,
// 14/13 CTA imbalance instead of 7/6) + rotating 4-deep load pipeline
// (reload slot immediately after consumption -> 4 LDG.128 always in flight)
// + streaming stores so output never evicts the L2-resident input.

#define NTHREADS 128
#define NBLOCKS  2048
#define ITEMS    8
#define TSTRIDE  (NTHREADS * NBLOCKS)   // 262144 float4s between a thread's items

__device__ __forceinline__ float4 proc(float4 xv, float w0, float w1,
                                       float w2, float w3)
{
    float c0 = __cosf(fmaf(2.0f, xv.x, w0));
    float c1 = __cosf(fmaf(2.0f, xv.y, w1));
    float c2 = __cosf(fmaf(2.0f, xv.z, w2));
    float c3 = __cosf(fmaf(2.0f, xv.w, w3));
    float t01  = c0 * c1;
    float t012 = t01 * c2;
    float4 o;
    o.x = c1 * c2 * c3;
    o.y = t01;
    o.z = t012;
    o.w = t012 * c3;
    return o;
}

__device__ __forceinline__ void store_cs(float4* p, float4 v)
{
    asm volatile("st.global.cs.v4.f32 [%0], {%1,%2,%3,%4};"
                 :: "l"(p), "f"(v.x), "f"(v.y), "f"(v.z), "f"(v.w)
                 : "memory");
}

// Fast path: n == ITEMS * TSTRIDE exactly (BATCH = 2^21).
__global__ void __launch_bounds__(NTHREADS, 16)
hilbert_fast(const float4* __restrict__ x4,
             const float* __restrict__ w,
             float4* __restrict__ out4)
{
    int tid = blockIdx.x * NTHREADS + threadIdx.x;

    float w0 = 2.0f * w[0], w1 = 2.0f * w[1];
    float w2 = 2.0f * w[2], w3 = 2.0f * w[3];

    // prologue: fill 4 pipeline slots
    float4 v[4];
#pragma unroll
    for (int k = 0; k < 4; k++)
        v[k] = x4[tid + k * TSTRIDE];

    // steady state: consume slot, immediately refill it, store result
#pragma unroll
    for (int k = 0; k < ITEMS; k++) {
        float4 o = proc(v[k & 3], w0, w1, w2, w3);
        if (k + 4 < ITEMS)
            v[k & 3] = x4[tid + (k + 4) * TSTRIDE];   // WAR on consumed slot
        store_cs(&out4[tid + k * TSTRIDE], o);
    }
}

// Generic fallback (any n of float4s).
__global__ void __launch_bounds__(256)
hilbert_generic(const float4* __restrict__ x4,
                const float* __restrict__ w,
                float4* __restrict__ out4, int n)
{
    int i = blockIdx.x * blockDim.x + threadIdx.x;
    if (i >= n) return;
    float w0 = 2.0f * w[0], w1 = 2.0f * w[1];
    float w2 = 2.0f * w[2], w3 = 2.0f * w[3];
    out4[i] = proc(x4[i], w0, w1, w2, w3);
}

extern "C" void kernel_launch(void* const* d_in, const int* in_sizes, int n_in,
                              void* d_out, int out_size)
{
    const float* x = (const float*)d_in[0];
    const float* w = (const float*)d_in[1];
    int nx = in_sizes[0];
    if (n_in >= 2 && in_sizes[0] < in_sizes[1]) {
        x = (const float*)d_in[1];
        w = (const float*)d_in[0];
        nx = in_sizes[1];
    }

    int n = nx / 4;  // float4 count (= batch)

    if (n == ITEMS * TSTRIDE) {
        hilbert_fast<<<NBLOCKS, NTHREADS>>>(
            (const float4*)x, w, (float4*)d_out);
    } else {
        int threads = 256;
        int blocks = (n + threads - 1) / threads;
        hilbert_generic<<<blocks, threads>>>(
            (const float4*)x, w, (float4*)d_out, n);
    }
}